// round 13
// baseline (speedup 1.0000x reference)
#include <cuda_runtime.h>
#include <cstdint>

// Problem constants
#define B_ 64
#define L_ 512
#define P_ 64
#define A_ 16
#define F_ 80
#define D_ 512

// Scan organization
#define CSZ 8       // CTAs per cluster (column split of R)
#define NCL 16      // clusters (B_/ROWS)
#define ROWS 4      // batch rows per cluster
#define COLS 64     // columns per CTA
#define THREADS 512

// Scratch
__device__ float g_ci[B_ * L_ * D_];      // tanh(x@W_ci+b)
__device__ float g_part[B_ * CSZ * L_];   // per-CTA cumulative output partials

// ---- f32x2 helpers --------------------------------------------------------
__device__ __forceinline__ unsigned long long pk2(float lo, float hi) {
    unsigned long long r;
    asm("mov.b64 %0, {%1,%2};" : "=l"(r) : "f"(lo), "f"(hi));
    return r;
}
__device__ __forceinline__ void fma2(unsigned long long& d, unsigned long long a, unsigned long long b) {
    asm("fma.rn.f32x2 %0, %1, %2, %0;" : "+l"(d) : "l"(a), "l"(b));
}
__device__ __forceinline__ float hadd2(unsigned long long v) {
    float lo, hi;
    asm("mov.b64 {%0,%1}, %2;" : "=f"(lo), "=f"(hi) : "l"(v));
    return lo + hi;
}

// ---- mbarrier / bulk-DSMEM helpers ----------------------------------------
__device__ __forceinline__ void mbar_init(uint32_t addr, uint32_t cnt) {
    asm volatile("mbarrier.init.shared.b64 [%0], %1;" :: "r"(addr), "r"(cnt) : "memory");
}
__device__ __forceinline__ void mbar_expect_tx(uint32_t addr, uint32_t bytes) {
    asm volatile("mbarrier.arrive.expect_tx.shared.b64 _, [%0], %1;"
                 :: "r"(addr), "r"(bytes) : "memory");
}
__device__ __forceinline__ void mbar_wait_cta(uint32_t addr, uint32_t parity) {
    uint32_t done;
    asm volatile(
        "{\n\t.reg .pred p;\n\t"
        "mbarrier.try_wait.parity.acquire.cta.shared::cta.b64 p, [%1], %2;\n\t"
        "selp.b32 %0, 1, 0, p;\n\t}"
        : "=r"(done) : "r"(addr), "r"(parity) : "memory");
    if (!done) {
        asm volatile(
            "{\n\t.reg .pred P1;\n\t"
            "WL_%=:\n\t"
            "mbarrier.try_wait.parity.acquire.cta.shared::cta.b64 P1, [%0], %1, 0x989680;\n\t"
            "@P1 bra.uni WD_%=;\n\t"
            "bra.uni WL_%=;\n\t"
            "WD_%=:\n\t}"
            :: "r"(addr), "r"(parity) : "memory");
    }
}
__device__ __forceinline__ void bulk_dsmem(uint32_t dst, uint32_t src,
                                           uint32_t bytes, uint32_t mbar) {
    asm volatile(
        "cp.async.bulk.shared::cluster.shared::cta.mbarrier::complete_tx::bytes "
        "[%0], [%1], %2, [%3];"
        :: "r"(dst), "r"(src), "r"(bytes), "r"(mbar) : "memory");
}
__device__ __forceinline__ void fence_proxy_async_cta() {
    asm volatile("fence.proxy.async.shared::cta;" ::: "memory");
}

// ============================================================================
// Kernel 1: ci = tanh(x @ W_ci + b_ci)  — R12 version (129 us), unchanged
// ============================================================================
#define XST 68

__global__ __launch_bounds__(256)
void k_ci(const float* __restrict__ obs, const float* __restrict__ act,
          const float* __restrict__ W, const float* __restrict__ bci)
{
    __shared__ float xs_t[80 * XST];
    __shared__ float ws[80 * 64];

    const int tid  = threadIdx.x;
    const int row0 = blockIdx.y * 64;
    const int d0   = blockIdx.x * 64;

    for (int idx = tid; idx < 64 * 80; idx += 256) {
        int r = idx / 80, c = idx % 80;
        int blg = row0 + r;
        int b = blg >> 9, l = blg & 511;
        float v = (c < 64) ? obs[(b * L_ + l) * P_ + c]
                           : act[(b * L_ + l) * A_ + (c - 64)];
        xs_t[c * XST + r] = v;
    }
    for (int idx = tid; idx < 80 * 64; idx += 256) {
        int k = idx >> 6, d = idx & 63;
        ws[k * 64 + d] = W[k * D_ + d0 + d];
    }
    __syncthreads();

    const int tx = tid & 15, ty = tid >> 4;
    float acc[4][4] = {};
#pragma unroll
    for (int k = 0; k < 80; k++) {
        float4 av = *(const float4*)&xs_t[k * XST + ty * 4];
        float4 bv = *(const float4*)&ws[k * 64 + tx * 4];
        acc[0][0] += av.x * bv.x; acc[0][1] += av.x * bv.y; acc[0][2] += av.x * bv.z; acc[0][3] += av.x * bv.w;
        acc[1][0] += av.y * bv.x; acc[1][1] += av.y * bv.y; acc[1][2] += av.y * bv.z; acc[1][3] += av.y * bv.w;
        acc[2][0] += av.z * bv.x; acc[2][1] += av.z * bv.y; acc[2][2] += av.z * bv.z; acc[2][3] += av.z * bv.w;
        acc[3][0] += av.w * bv.x; acc[3][1] += av.w * bv.y; acc[3][2] += av.w * bv.z; acc[3][3] += av.w * bv.w;
    }

    float bi0 = bci[d0 + tx * 4 + 0];
    float bi1 = bci[d0 + tx * 4 + 1];
    float bi2 = bci[d0 + tx * 4 + 2];
    float bi3 = bci[d0 + tx * 4 + 3];
#pragma unroll
    for (int ii = 0; ii < 4; ii++) {
        int blg = row0 + ty * 4 + ii;
        float4 o;
        o.x = tanhf(acc[ii][0] + bi0);
        o.y = tanhf(acc[ii][1] + bi1);
        o.z = tanhf(acc[ii][2] + bi2);
        o.w = tanhf(acc[ii][3] + bi3);
        *(float4*)&g_ci[blg * D_ + d0 + tx * 4] = o;
    }
}

// ============================================================================
// Kernel 2: the scan — single-phase epilogue.
//  thread = (col, ks): 1 col, 64-row k-slice, 4 batches; R k-packed (64 regs)
//  h slice-major hbuf[buf][ks][b][64], slice stride 260 floats (bank-spread)
//  shfl-allreduce over ks; lanes 0-15/warp gate+update; h carried in register
//  DMA/mbar protocol IDENTICAL to R10 (1 KB slices, 1 barrier/buffer, TX 7168)
//
// SMEM (floats): hbuf [0, 6240) = 3 x 8 x 260 ; osum [6240, 6304)
//                mbar @ byte 25216 (3 x 8 B)
// ============================================================================
#define SLICE_STRIDE 260                        // floats (1040 B, 16B-aligned)
#define HB_STRIDE    (CSZ * SLICE_STRIDE)       // 2080 floats
#define HBUF_OFF  0
#define OSUM_OFF  6240
#define MBAR_BYTE 25216
#define SMEM_BYTES (MBAR_BYTE + 64)

#define SLICE_BYTES 1024                        // content: 4 b x 64 cols x 4 B
#define STEP_TX     ((CSZ - 1) * SLICE_BYTES)   // 7168

extern __shared__ float smem_f[];

__global__ void __cluster_dims__(CSZ, 1, 1) __launch_bounds__(THREADS, 1)
k_scan(const float* __restrict__ R, const float* __restrict__ b_ig,
       const float* __restrict__ W_out)
{
    float* hbuf = smem_f + HBUF_OFF;
    float* osum = smem_f + OSUM_OFF;

    const uint32_t smem_u32 = (uint32_t)__cvta_generic_to_shared(smem_f);

    const int tid = threadIdx.x;
    const int c   = blockIdx.x;          // cluster rank / column slice
    const int b0  = blockIdx.y * ROWS;
    const int j0  = c * COLS;

    const int w  = tid >> 5;
    const int l  = tid & 31;
    const int ks = l >> 2;               // k-slice 0..7 (64 rows each)
    const int jcol = w * 4 + (l & 3);    // this thread's column 0..63

    // output-lane constants (lanes 0-15 of each warp)
    const int ob   = l >> 2;             // batch 0..3  (l<16)
    const int ocol = w * 4 + (l & 3);    // column
    float biasr = 0.0f, wslr = 0.0f;
    if (l < 16) {
        biasr = b_ig[j0 + ocol];
        wslr  = W_out[j0 + ocol];
    }

    // ---- R k-pairs into registers: rows ks*64..+63 of column jcol ----
    unsigned long long rp[32];
    {
        const float* rg = R + j0 + jcol;
#pragma unroll
        for (int m = 0; m < 32; m++) {
            float v0 = rg[(ks * 64 + 2 * m)     * D_];
            float v1 = rg[(ks * 64 + 2 * m + 1) * D_];
            rp[m] = pk2(v0, v1);
        }
    }

    // ---- init smem ----
    for (int idx = tid; idx < 3 * HB_STRIDE; idx += THREADS) hbuf[idx] = 0.0f;
    if (tid < 64) osum[tid] = 0.0f;
    if (tid == 0) {
        mbar_init(smem_u32 + MBAR_BYTE + 0,  1);
        mbar_init(smem_u32 + MBAR_BYTE + 8,  1);
        mbar_init(smem_u32 + MBAR_BYTE + 16, 1);
    }
    __syncthreads();
    if (tid == 0) {
        mbar_expect_tx(smem_u32 + MBAR_BYTE + 0,  STEP_TX);
        mbar_expect_tx(smem_u32 + MBAR_BYTE + 8,  STEP_TX);
        mbar_expect_tx(smem_u32 + MBAR_BYTE + 16, STEP_TX);
    }
    __syncthreads();
    asm volatile("barrier.cluster.arrive.aligned;" ::: "memory");
    asm volatile("barrier.cluster.wait.aligned;"   ::: "memory");

    // DMA threads (tid<8) need only THEIR peer base
    uint32_t pbase = 0;
    if (tid < CSZ) {
        asm volatile("mapa.shared::cluster.u32 %0, %1, %2;"
                     : "=r"(pbase) : "r"(smem_u32), "r"(tid));
    }

    float hreg = 0.0f;     // lanes 0-15: this lane's h[ob][ocol] (own slice)
    float racc = 0.0f;
    int cur = 0;
    uint32_t phases = 0;

    for (int t = 0; t < L_; t++) {
        const int nxt = (cur == 2) ? 0 : cur + 1;

        // prefetch ci (lanes 0-15 of each warp; consumed after matvec)
        float civ = 0.0f;
        if (l < 16)
            civ = __ldg(&g_ci[((b0 + ob) * L_ + t) * D_ + j0 + ocol]);

        // deferred output partial from step t-1 (pre-wait, off critical path)
        if (t > 0 && tid < 4) {
            float s = 0.0f;
#pragma unroll
            for (int g = 0; g < 16; g++) s += osum[g * 4 + tid];
            racc += s;
            g_part[(b0 + tid) * (CSZ * L_) + c * L_ + (t - 1)] = racc;
        }

        // wait for h(t) remote slices (skip t=0: zeros written locally)
        if (t > 0) {
            mbar_wait_cta(smem_u32 + MBAR_BYTE + cur * 8, (phases >> cur) & 1u);
            phases ^= (1u << cur);
            if (tid == 256)
                mbar_expect_tx(smem_u32 + MBAR_BYTE + cur * 8, STEP_TX);
        }

        // ---- matvec: k-packed R regs x slice-major h (no per-iter MOVs) ----
        const float* hc = hbuf + cur * HB_STRIDE + ks * SLICE_STRIDE;
        unsigned long long a0 = 0, a1 = 0, a2 = 0, a3 = 0;
#pragma unroll
        for (int m2 = 0; m2 < 16; m2++) {
            ulonglong2 h0 = *(const ulonglong2*)(hc + 0 * 64 + 4 * m2);
            ulonglong2 h1 = *(const ulonglong2*)(hc + 1 * 64 + 4 * m2);
            ulonglong2 h2 = *(const ulonglong2*)(hc + 2 * 64 + 4 * m2);
            ulonglong2 h3 = *(const ulonglong2*)(hc + 3 * 64 + 4 * m2);
            fma2(a0, rp[2 * m2], h0.x); fma2(a0, rp[2 * m2 + 1], h0.y);
            fma2(a1, rp[2 * m2], h1.x); fma2(a1, rp[2 * m2 + 1], h1.y);
            fma2(a2, rp[2 * m2], h2.x); fma2(a2, rp[2 * m2 + 1], h2.y);
            fma2(a3, rp[2 * m2], h3.x); fma2(a3, rp[2 * m2 + 1], h3.y);
        }
        float z0 = hadd2(a0), z1 = hadd2(a1), z2 = hadd2(a2), z3 = hadd2(a3);
        // allreduce over ks (lanes l, l^4, l^8, ... share the same column)
#pragma unroll
        for (int off = 4; off <= 16; off <<= 1) {
            z0 += __shfl_xor_sync(0xFFFFFFFF, z0, off);
            z1 += __shfl_xor_sync(0xFFFFFFFF, z1, off);
            z2 += __shfl_xor_sync(0xFFFFFFFF, z2, off);
            z3 += __shfl_xor_sync(0xFFFFFFFF, z3, off);
        }

        // ---- gate + update (lanes 0-15: one (col, batch) each) ----
        if (l < 16) {
            float z = (ob == 0) ? z0 : (ob == 1) ? z1 : (ob == 2) ? z2 : z3;
            z += biasr;
            float ig = 1.0f / (1.0f + __expf(-z));
            float u  = civ * ig;
            hreg += u;
            hbuf[nxt * HB_STRIDE + c * SLICE_STRIDE + ob * 64 + ocol] = hreg;

            float pp = u * wslr;
            pp += __shfl_xor_sync(0x0000FFFF, pp, 1);
            pp += __shfl_xor_sync(0x0000FFFF, pp, 2);
            if ((l & 3) == 0)
                osum[w * 4 + ob] = pp;
        }
        __syncthreads();

        // ---- DMA h(t+1) own slice to the 7 remote peers ----
        if (t + 1 < L_ && tid < CSZ && tid != c) {
            fence_proxy_async_cta();
            uint32_t off  = (uint32_t)(HBUF_OFF + nxt * HB_STRIDE + c * SLICE_STRIDE) * 4u;
            uint32_t moff = (uint32_t)(MBAR_BYTE + nxt * 8);
            bulk_dsmem(pbase + off, smem_u32 + off, SLICE_BYTES, pbase + moff);
        }

        cur = nxt;
    }

    // final deferred output partial (t = L-1)
    if (tid < 4) {
        float s = 0.0f;
#pragma unroll
        for (int g = 0; g < 16; g++) s += osum[g * 4 + tid];
        racc += s;
        g_part[(b0 + tid) * (CSZ * L_) + c * L_ + (L_ - 1)] = racc;
    }

    asm volatile("barrier.cluster.arrive.aligned;" ::: "memory");
    asm volatile("barrier.cluster.wait.aligned;"   ::: "memory");
}

// ============================================================================
// Kernel 3: out[b,t] = b_out + sum_c g_part[b][c][t]
// ============================================================================
__global__ __launch_bounds__(256)
void k_out(const float* __restrict__ b_out, float* __restrict__ out)
{
    int i = blockIdx.x * 256 + threadIdx.x;
    int b = i >> 9, t = i & 511;
    float s = b_out[0];
#pragma unroll
    for (int cc = 0; cc < CSZ; cc++) s += g_part[b * (CSZ * L_) + cc * L_ + t];
    out[i] = s;
}

// ============================================================================
extern "C" void kernel_launch(void* const* d_in, const int* in_sizes, int n_in,
                              void* d_out, int out_size)
{
    const float* obs  = (const float*)d_in[0];
    const float* act  = (const float*)d_in[1];
    const float* W_ci = (const float*)d_in[2];
    const float* b_ci = (const float*)d_in[3];
    const float* R    = (const float*)d_in[4];
    const float* bg   = (const float*)d_in[5];
    const float* W_o  = (const float*)d_in[6];
    const float* b_o  = (const float*)d_in[7];
    float* out = (float*)d_out;

    k_ci<<<dim3(8, 512), 256>>>(obs, act, W_ci, b_ci);

    cudaFuncSetAttribute(k_scan, cudaFuncAttributeMaxDynamicSharedMemorySize, SMEM_BYTES);
    k_scan<<<dim3(CSZ, NCL), THREADS, SMEM_BYTES>>>(R, bg, W_o);

    k_out<<<128, 256>>>(b_o, out);
}

// round 14
// speedup vs baseline: 1.3841x; 1.3841x over previous
#include <cuda_runtime.h>
#include <cstdint>

// Problem constants
#define B_ 64
#define L_ 512
#define P_ 64
#define A_ 16
#define F_ 80
#define D_ 512

// Scan organization
#define CSZ 8       // CTAs per cluster (column split of R)
#define NCL 16      // clusters (B_/ROWS)
#define ROWS 4      // batch rows per cluster
#define COLS 64     // columns per CTA
#define KROWS 32    // rows per warp k-slice (16 warps)
#define THREADS 512

// Scratch
__device__ float g_ci[B_ * L_ * D_];      // tanh(x@W_ci+b)
__device__ float g_part[B_ * CSZ * L_];   // per-CTA cumulative output partials

// ---- f32x2 helpers --------------------------------------------------------
__device__ __forceinline__ unsigned long long pk2(float lo, float hi) {
    unsigned long long r;
    asm("mov.b64 %0, {%1,%2};" : "=l"(r) : "f"(lo), "f"(hi));
    return r;
}
__device__ __forceinline__ void fma2(unsigned long long& d, unsigned long long a, unsigned long long b) {
    asm("fma.rn.f32x2 %0, %1, %2, %0;" : "+l"(d) : "l"(a), "l"(b));
}
__device__ __forceinline__ void upk2(float& lo, float& hi, unsigned long long v) {
    asm("mov.b64 {%0,%1}, %2;" : "=f"(lo), "=f"(hi) : "l"(v));
}

// ---- mbarrier / bulk-DSMEM helpers ----------------------------------------
__device__ __forceinline__ void mbar_init(uint32_t addr, uint32_t cnt) {
    asm volatile("mbarrier.init.shared.b64 [%0], %1;" :: "r"(addr), "r"(cnt) : "memory");
}
__device__ __forceinline__ void mbar_expect_tx(uint32_t addr, uint32_t bytes) {
    asm volatile("mbarrier.arrive.expect_tx.shared.b64 _, [%0], %1;"
                 :: "r"(addr), "r"(bytes) : "memory");
}
__device__ __forceinline__ void mbar_wait_cta(uint32_t addr, uint32_t parity) {
    uint32_t done;
    asm volatile(
        "{\n\t.reg .pred p;\n\t"
        "mbarrier.try_wait.parity.acquire.cta.shared::cta.b64 p, [%1], %2;\n\t"
        "selp.b32 %0, 1, 0, p;\n\t}"
        : "=r"(done) : "r"(addr), "r"(parity) : "memory");
    if (!done) {
        asm volatile(
            "{\n\t.reg .pred P1;\n\t"
            "WL_%=:\n\t"
            "mbarrier.try_wait.parity.acquire.cta.shared::cta.b64 P1, [%0], %1, 0x989680;\n\t"
            "@P1 bra.uni WD_%=;\n\t"
            "bra.uni WL_%=;\n\t"
            "WD_%=:\n\t}"
            :: "r"(addr), "r"(parity) : "memory");
    }
}
__device__ __forceinline__ void bulk_dsmem(uint32_t dst, uint32_t src,
                                           uint32_t bytes, uint32_t mbar) {
    asm volatile(
        "cp.async.bulk.shared::cluster.shared::cta.mbarrier::complete_tx::bytes "
        "[%0], [%1], %2, [%3];"
        :: "r"(dst), "r"(src), "r"(bytes), "r"(mbar) : "memory");
}
__device__ __forceinline__ void fence_proxy_async_cta() {
    asm volatile("fence.proxy.async.shared::cta;" ::: "memory");
}

extern __shared__ float smem_f[];

// ============================================================================
// Kernel 1: ci = tanh(x @ W_ci + b_ci)
// 128x128 tile, 8x8 per thread (was 64x64 / 4x4): FMA:LDS ratio doubled.
// Dynamic smem 83.2 KB (2 CTAs/SM). k-loop unrolled by 4 (I$-friendly body).
// ============================================================================
#define XST2 132                    // padded row stride for 128 rows
#define KCI_SMEM ((80 * XST2 + 80 * 128) * 4)   // 83200 B

__global__ __launch_bounds__(256)
void k_ci(const float* __restrict__ obs, const float* __restrict__ act,
          const float* __restrict__ W, const float* __restrict__ bci)
{
    float* xs_t = smem_f;               // [k][row]  80 x 132
    float* ws   = smem_f + 80 * XST2;   // [k][d]    80 x 128

    const int tid  = threadIdx.x;
    const int row0 = blockIdx.y * 128;  // bl tile
    const int d0   = blockIdx.x * 128;  // d tile

    for (int idx = tid; idx < 128 * 80; idx += 256) {
        int r = idx / 80, c = idx % 80;
        int blg = row0 + r;
        int b = blg >> 9, l = blg & 511;
        float v = (c < 64) ? obs[(b * L_ + l) * P_ + c]
                           : act[(b * L_ + l) * A_ + (c - 64)];
        xs_t[c * XST2 + r] = v;
    }
    for (int idx = tid; idx < 80 * 128; idx += 256) {
        int k = idx >> 7, d = idx & 127;
        ws[k * 128 + d] = W[k * D_ + d0 + d];
    }
    __syncthreads();

    const int tx = tid & 15, ty = tid >> 4;   // d group tx*8, bl group ty*8
    float acc[8][8] = {};
#pragma unroll 4
    for (int k = 0; k < 80; k++) {
        float4 a0 = *(const float4*)&xs_t[k * XST2 + ty * 8];
        float4 a1 = *(const float4*)&xs_t[k * XST2 + ty * 8 + 4];
        float4 bv0 = *(const float4*)&ws[k * 128 + tx * 8];
        float4 bv1 = *(const float4*)&ws[k * 128 + tx * 8 + 4];
        float a[8] = {a0.x, a0.y, a0.z, a0.w, a1.x, a1.y, a1.z, a1.w};
        float b[8] = {bv0.x, bv0.y, bv0.z, bv0.w, bv1.x, bv1.y, bv1.z, bv1.w};
#pragma unroll
        for (int i = 0; i < 8; i++)
#pragma unroll
            for (int j = 0; j < 8; j++)
                acc[i][j] += a[i] * b[j];
    }

    float bi[8];
#pragma unroll
    for (int j = 0; j < 8; j++) bi[j] = bci[d0 + tx * 8 + j];

#pragma unroll
    for (int i = 0; i < 8; i++) {
        int blg = row0 + ty * 8 + i;
        float4 o0, o1;
        o0.x = tanhf(acc[i][0] + bi[0]);
        o0.y = tanhf(acc[i][1] + bi[1]);
        o0.z = tanhf(acc[i][2] + bi[2]);
        o0.w = tanhf(acc[i][3] + bi[3]);
        o1.x = tanhf(acc[i][4] + bi[4]);
        o1.y = tanhf(acc[i][5] + bi[5]);
        o1.z = tanhf(acc[i][6] + bi[6]);
        o1.w = tanhf(acc[i][7] + bi[7]);
        *(float4*)&g_ci[blg * D_ + d0 + tx * 8]     = o0;
        *(float4*)&g_ci[blg * D_ + d0 + tx * 8 + 4] = o1;
    }
}

// ============================================================================
// Kernel 2: the scan — EXACT R10/R12 code (1474 us best). FROZEN.
// ============================================================================
#define HBUF_OFF  0
#define PBUF_OFF  6144
#define BIAS_OFF  10240
#define WSL_OFF   10304
#define OSUM_OFF  10368
#define MBAR_BYTE 41600
#define SMEM_BYTES (MBAR_BYTE + 64)

#define SLICE_BYTES 1024                       // 64 cols x 4 batches x 4 B
#define STEP_TX     ((CSZ - 1) * SLICE_BYTES)  // 7168 (self-copy skipped)

__global__ void __cluster_dims__(CSZ, 1, 1) __launch_bounds__(THREADS, 1)
k_scan(const float* __restrict__ R, const float* __restrict__ b_ig,
       const float* __restrict__ W_out)
{
    float* hbuf = smem_f + HBUF_OFF;
    float* pbuf = smem_f + PBUF_OFF;
    float* bias = smem_f + BIAS_OFF;
    float* wsl  = smem_f + WSL_OFF;
    float* osum = smem_f + OSUM_OFF;

    const uint32_t smem_u32 = (uint32_t)__cvta_generic_to_shared(smem_f);

    const int tid = threadIdx.x;
    const int c   = blockIdx.x;          // cluster rank / column slice
    const int b0  = blockIdx.y * ROWS;
    const int j0  = c * COLS;

    const int ks = tid >> 5;             // warp = k-slice (0..15)
    const int jp = tid & 31;             // cols 2jp, 2jp+1
    const int jj = tid >> 2;             // reduce mapping (tid<256)
    const int bb = tid & 3;

    // ---- R slice into registers ----
    float rx[KROWS], ry[KROWS];
    {
        const float* rg = R + j0 + 2 * jp;
#pragma unroll
        for (int ii = 0; ii < KROWS; ii++) {
            float2 v = *(const float2*)(rg + (ks * KROWS + ii) * D_);
            rx[ii] = v.x; ry[ii] = v.y;
        }
    }

    // ---- init smem ----
    for (int idx = tid; idx < 3 * D_ * ROWS; idx += THREADS) hbuf[idx] = 0.0f;
    if (tid < COLS) {
        bias[tid] = b_ig[j0 + tid];
        wsl[tid]  = W_out[j0 + tid];
    }
    if (tid < 32) osum[tid] = 0.0f;
    if (tid == 0) {
        mbar_init(smem_u32 + MBAR_BYTE + 0,  1);
        mbar_init(smem_u32 + MBAR_BYTE + 8,  1);
        mbar_init(smem_u32 + MBAR_BYTE + 16, 1);
    }
    __syncthreads();
    if (tid == 0) {
        mbar_expect_tx(smem_u32 + MBAR_BYTE + 0,  STEP_TX);
        mbar_expect_tx(smem_u32 + MBAR_BYTE + 8,  STEP_TX);
        mbar_expect_tx(smem_u32 + MBAR_BYTE + 16, STEP_TX);
    }
    __syncthreads();
    asm volatile("barrier.cluster.arrive.aligned;" ::: "memory");
    asm volatile("barrier.cluster.wait.aligned;"   ::: "memory");

    // Peer smem bases
    uint32_t peer_base[CSZ];
#pragma unroll
    for (int p = 0; p < CSZ; p++) {
        asm volatile("mapa.shared::cluster.u32 %0, %1, %2;"
                     : "=r"(peer_base[p]) : "r"(smem_u32), "r"(p));
    }

    float racc = 0.0f;
    int cur = 0;
    uint32_t phases = 0;   // bit b = next wait parity for buffer b

    for (int t = 0; t < L_; t++) {
        const int nxt = (cur == 2) ? 0 : cur + 1;

        // prefetch ci (consumed after matvec)
        float civ = 0.0f;
        if (tid < 256)
            civ = __ldg(&g_ci[((b0 + bb) * L_ + t) * D_ + j0 + jj]);

        // deferred output partial from step t-1 (pre-wait, off critical path)
        if (t > 0 && tid < 4) {
            float s = 0.0f;
#pragma unroll
            for (int w = 0; w < 8; w++) s += osum[w * 4 + tid];
            racc += s;
            g_part[(b0 + tid) * (CSZ * L_) + c * L_ + (t - 1)] = racc;
        }

        // wait for h(t) remote slices (skip t=0: zeros written locally)
        if (t > 0) {
            mbar_wait_cta(smem_u32 + MBAR_BYTE + cur * 8, (phases >> cur) & 1u);
            phases ^= (1u << cur);
            // re-post expect for this buffer's NEXT fill round (at step t+2)
            if (tid == 256)
                mbar_expect_tx(smem_u32 + MBAR_BYTE + cur * 8, STEP_TX);
        }

        const float* hc = hbuf + cur * (D_ * ROWS);

        // ---- matvec: R from registers, h broadcast from smem ----
        {
            const ulonglong2* hvp = (const ulonglong2*)(hc + ks * KROWS * ROWS);
            unsigned long long a00 = 0, a01 = 0, a10 = 0, a11 = 0;
#pragma unroll
            for (int ii = 0; ii < KROWS; ii++) {
                ulonglong2 hv = hvp[ii];
                unsigned long long r0 = pk2(rx[ii], rx[ii]);
                unsigned long long r1 = pk2(ry[ii], ry[ii]);
                fma2(a00, r0, hv.x); fma2(a01, r0, hv.y);
                fma2(a10, r1, hv.x); fma2(a11, r1, hv.y);
            }
            float4 q0, q1;
            upk2(q0.x, q0.y, a00); upk2(q0.z, q0.w, a01);
            upk2(q1.x, q1.y, a10); upk2(q1.z, q1.w, a11);
            float* pb = pbuf + (ks * 32 + jp) * 8;
            *(float4*)(pb)     = q0;
            *(float4*)(pb + 4) = q1;
        }
        __syncthreads();

        // ---- reduce + gate + update: write h(t+1) own slice locally ----
        if (tid < 256) {
            float z = bias[jj];
#pragma unroll
            for (int s = 0; s < 16; s++) z += pbuf[s * 256 + tid];
            float ig = 1.0f / (1.0f + __expf(-z));
            float u  = civ * ig;
            float hval = hc[(j0 + jj) * 4 + bb] + u;
            hbuf[nxt * (D_ * ROWS) + (j0 + jj) * 4 + bb] = hval;

            float pp = u * wsl[jj];
            pp += __shfl_xor_sync(0xFFFFFFFF, pp, 4);
            pp += __shfl_xor_sync(0xFFFFFFFF, pp, 8);
            pp += __shfl_xor_sync(0xFFFFFFFF, pp, 16);
            if ((tid & 31) < 4)
                osum[(tid >> 5) * 4 + bb] = pp;
        }
        __syncthreads();

        // ---- DMA h(t+1) own slice to the 7 REMOTE peers (skip self) ----
        if (t + 1 < L_ && tid < CSZ && tid != c) {
            fence_proxy_async_cta();
            uint32_t off  = (uint32_t)(HBUF_OFF + nxt * (D_ * ROWS) + j0 * 4) * 4u;
            uint32_t moff = (uint32_t)(MBAR_BYTE + nxt * 8);
            bulk_dsmem(peer_base[tid] + off, smem_u32 + off, SLICE_BYTES,
                       peer_base[tid] + moff);
        }

        cur = nxt;
    }

    // final deferred output partial (t = L-1)
    if (tid < 4) {
        float s = 0.0f;
#pragma unroll
        for (int w = 0; w < 8; w++) s += osum[w * 4 + tid];
        racc += s;
        g_part[(b0 + tid) * (CSZ * L_) + c * L_ + (L_ - 1)] = racc;
    }

    asm volatile("barrier.cluster.arrive.aligned;" ::: "memory");
    asm volatile("barrier.cluster.wait.aligned;"   ::: "memory");
}

// ============================================================================
// Kernel 3: out[b,t] = b_out + sum_c g_part[b][c][t]
// ============================================================================
__global__ __launch_bounds__(256)
void k_out(const float* __restrict__ b_out, float* __restrict__ out)
{
    int i = blockIdx.x * 256 + threadIdx.x;
    int b = i >> 9, t = i & 511;
    float s = b_out[0];
#pragma unroll
    for (int cc = 0; cc < CSZ; cc++) s += g_part[b * (CSZ * L_) + cc * L_ + t];
    out[i] = s;
}

// ============================================================================
extern "C" void kernel_launch(void* const* d_in, const int* in_sizes, int n_in,
                              void* d_out, int out_size)
{
    const float* obs  = (const float*)d_in[0];
    const float* act  = (const float*)d_in[1];
    const float* W_ci = (const float*)d_in[2];
    const float* b_ci = (const float*)d_in[3];
    const float* R    = (const float*)d_in[4];
    const float* bg   = (const float*)d_in[5];
    const float* W_o  = (const float*)d_in[6];
    const float* b_o  = (const float*)d_in[7];
    float* out = (float*)d_out;

    cudaFuncSetAttribute(k_ci, cudaFuncAttributeMaxDynamicSharedMemorySize, KCI_SMEM);
    k_ci<<<dim3(4, 256), 256, KCI_SMEM>>>(obs, act, W_ci, b_ci);

    cudaFuncSetAttribute(k_scan, cudaFuncAttributeMaxDynamicSharedMemorySize, SMEM_BYTES);
    k_scan<<<dim3(CSZ, NCL), THREADS, SMEM_BYTES>>>(R, bg, W_o);

    k_out<<<128, 256>>>(b_o, out);
}

// round 15
// speedup vs baseline: 1.3955x; 1.0082x over previous
#include <cuda_runtime.h>
#include <cstdint>

// Problem constants
#define B_ 64
#define L_ 512
#define P_ 64
#define A_ 16
#define F_ 80
#define D_ 512

// Scan organization
#define CSZ 8       // CTAs per cluster (column split of R)
#define NCL 16      // clusters (B_/ROWS)
#define ROWS 4      // batch rows per cluster
#define COLS 64     // columns per CTA
#define KROWS 32    // rows per warp k-slice (16 warps)
#define THREADS 512

// Scratch
__device__ float g_ci[B_ * L_ * D_];      // tanh(x@W_ci+b)
__device__ float g_part[B_ * CSZ * L_];   // per-CTA cumulative output partials

// ---- f32x2 helpers --------------------------------------------------------
__device__ __forceinline__ unsigned long long pk2(float lo, float hi) {
    unsigned long long r;
    asm("mov.b64 %0, {%1,%2};" : "=l"(r) : "f"(lo), "f"(hi));
    return r;
}
__device__ __forceinline__ void fma2(unsigned long long& d, unsigned long long a, unsigned long long b) {
    asm("fma.rn.f32x2 %0, %1, %2, %0;" : "+l"(d) : "l"(a), "l"(b));
}
__device__ __forceinline__ void upk2(float& lo, float& hi, unsigned long long v) {
    asm("mov.b64 {%0,%1}, %2;" : "=f"(lo), "=f"(hi) : "l"(v));
}

// ---- mbarrier / bulk-DSMEM helpers ----------------------------------------
__device__ __forceinline__ void mbar_init(uint32_t addr, uint32_t cnt) {
    asm volatile("mbarrier.init.shared.b64 [%0], %1;" :: "r"(addr), "r"(cnt) : "memory");
}
__device__ __forceinline__ void mbar_expect_tx(uint32_t addr, uint32_t bytes) {
    asm volatile("mbarrier.arrive.expect_tx.shared.b64 _, [%0], %1;"
                 :: "r"(addr), "r"(bytes) : "memory");
}
__device__ __forceinline__ void mbar_wait_cta(uint32_t addr, uint32_t parity) {
    uint32_t done;
    asm volatile(
        "{\n\t.reg .pred p;\n\t"
        "mbarrier.try_wait.parity.acquire.cta.shared::cta.b64 p, [%1], %2;\n\t"
        "selp.b32 %0, 1, 0, p;\n\t}"
        : "=r"(done) : "r"(addr), "r"(parity) : "memory");
    if (!done) {
        asm volatile(
            "{\n\t.reg .pred P1;\n\t"
            "WL_%=:\n\t"
            "mbarrier.try_wait.parity.acquire.cta.shared::cta.b64 P1, [%0], %1, 0x989680;\n\t"
            "@P1 bra.uni WD_%=;\n\t"
            "bra.uni WL_%=;\n\t"
            "WD_%=:\n\t}"
            :: "r"(addr), "r"(parity) : "memory");
    }
}
__device__ __forceinline__ void bulk_dsmem(uint32_t dst, uint32_t src,
                                           uint32_t bytes, uint32_t mbar) {
    asm volatile(
        "cp.async.bulk.shared::cluster.shared::cta.mbarrier::complete_tx::bytes "
        "[%0], [%1], %2, [%3];"
        :: "r"(dst), "r"(src), "r"(bytes), "r"(mbar) : "memory");
}
__device__ __forceinline__ void fence_proxy_async_cta() {
    asm volatile("fence.proxy.async.shared::cta;" ::: "memory");
}

extern __shared__ float smem_f[];

// ============================================================================
// Kernel 1: ci = tanh(x @ W_ci + b_ci)
// 128x128 tile, 8x8 per thread, FFMA2 over row-pairs:
//   A-side pairs come FREE from ulonglong2 loads of xs_t rows;
//   b duplicated via 8 pk2 (ALU pipe); 32 FFMA2 vs 64 FFMA per k per thread.
// Arithmetic order identical to R14 (bitwise-same result).
// ============================================================================
#define XST2 132                    // padded row stride for 128 rows
#define KCI_SMEM ((80 * XST2 + 80 * 128) * 4)   // 83200 B

__global__ __launch_bounds__(256)
void k_ci(const float* __restrict__ obs, const float* __restrict__ act,
          const float* __restrict__ W, const float* __restrict__ bci)
{
    float* xs_t = smem_f;               // [k][row]  80 x 132
    float* ws   = smem_f + 80 * XST2;   // [k][d]    80 x 128

    const int tid  = threadIdx.x;
    const int row0 = blockIdx.y * 128;  // bl tile
    const int d0   = blockIdx.x * 128;  // d tile

    for (int idx = tid; idx < 128 * 80; idx += 256) {
        int r = idx / 80, c = idx % 80;
        int blg = row0 + r;
        int b = blg >> 9, l = blg & 511;
        float v = (c < 64) ? obs[(b * L_ + l) * P_ + c]
                           : act[(b * L_ + l) * A_ + (c - 64)];
        xs_t[c * XST2 + r] = v;
    }
    for (int idx = tid; idx < 80 * 128; idx += 256) {
        int k = idx >> 7, d = idx & 127;
        ws[k * 128 + d] = W[k * D_ + d0 + d];
    }
    __syncthreads();

    const int tx = tid & 15, ty = tid >> 4;   // d group tx*8, bl group ty*8
    unsigned long long acc2[4][8] = {};        // (row 2i2, row 2i2+1) x col j
#pragma unroll 4
    for (int k = 0; k < 80; k++) {
        ulonglong2 av0 = *(const ulonglong2*)&xs_t[k * XST2 + ty * 8];      // (r0,r1),(r2,r3)
        ulonglong2 av1 = *(const ulonglong2*)&xs_t[k * XST2 + ty * 8 + 4];  // (r4,r5),(r6,r7)
        float4 bv0 = *(const float4*)&ws[k * 128 + tx * 8];
        float4 bv1 = *(const float4*)&ws[k * 128 + tx * 8 + 4];
        unsigned long long a2[4] = {av0.x, av0.y, av1.x, av1.y};
        unsigned long long b2[8];
        b2[0] = pk2(bv0.x, bv0.x); b2[1] = pk2(bv0.y, bv0.y);
        b2[2] = pk2(bv0.z, bv0.z); b2[3] = pk2(bv0.w, bv0.w);
        b2[4] = pk2(bv1.x, bv1.x); b2[5] = pk2(bv1.y, bv1.y);
        b2[6] = pk2(bv1.z, bv1.z); b2[7] = pk2(bv1.w, bv1.w);
#pragma unroll
        for (int i2 = 0; i2 < 4; i2++)
#pragma unroll
            for (int j = 0; j < 8; j++)
                fma2(acc2[i2][j], a2[i2], b2[j]);
    }

    float bi[8];
#pragma unroll
    for (int j = 0; j < 8; j++) bi[j] = bci[d0 + tx * 8 + j];

#pragma unroll
    for (int i2 = 0; i2 < 4; i2++) {
        float lo[8], hi[8];
#pragma unroll
        for (int j = 0; j < 8; j++) upk2(lo[j], hi[j], acc2[i2][j]);

        int blg0 = row0 + ty * 8 + 2 * i2;
        float4 o0, o1;
        o0.x = tanhf(lo[0] + bi[0]); o0.y = tanhf(lo[1] + bi[1]);
        o0.z = tanhf(lo[2] + bi[2]); o0.w = tanhf(lo[3] + bi[3]);
        o1.x = tanhf(lo[4] + bi[4]); o1.y = tanhf(lo[5] + bi[5]);
        o1.z = tanhf(lo[6] + bi[6]); o1.w = tanhf(lo[7] + bi[7]);
        *(float4*)&g_ci[blg0 * D_ + d0 + tx * 8]     = o0;
        *(float4*)&g_ci[blg0 * D_ + d0 + tx * 8 + 4] = o1;

        o0.x = tanhf(hi[0] + bi[0]); o0.y = tanhf(hi[1] + bi[1]);
        o0.z = tanhf(hi[2] + bi[2]); o0.w = tanhf(hi[3] + bi[3]);
        o1.x = tanhf(hi[4] + bi[4]); o1.y = tanhf(hi[5] + bi[5]);
        o1.z = tanhf(hi[6] + bi[6]); o1.w = tanhf(hi[7] + bi[7]);
        *(float4*)&g_ci[(blg0 + 1) * D_ + d0 + tx * 8]     = o0;
        *(float4*)&g_ci[(blg0 + 1) * D_ + d0 + tx * 8 + 4] = o1;
    }
}

// ============================================================================
// Kernel 2: the scan — EXACT R10/R12 code (best). FROZEN.
// ============================================================================
#define HBUF_OFF  0
#define PBUF_OFF  6144
#define BIAS_OFF  10240
#define WSL_OFF   10304
#define OSUM_OFF  10368
#define MBAR_BYTE 41600
#define SMEM_BYTES (MBAR_BYTE + 64)

#define SLICE_BYTES 1024                       // 64 cols x 4 batches x 4 B
#define STEP_TX     ((CSZ - 1) * SLICE_BYTES)  // 7168 (self-copy skipped)

__global__ void __cluster_dims__(CSZ, 1, 1) __launch_bounds__(THREADS, 1)
k_scan(const float* __restrict__ R, const float* __restrict__ b_ig,
       const float* __restrict__ W_out)
{
    float* hbuf = smem_f + HBUF_OFF;
    float* pbuf = smem_f + PBUF_OFF;
    float* bias = smem_f + BIAS_OFF;
    float* wsl  = smem_f + WSL_OFF;
    float* osum = smem_f + OSUM_OFF;

    const uint32_t smem_u32 = (uint32_t)__cvta_generic_to_shared(smem_f);

    const int tid = threadIdx.x;
    const int c   = blockIdx.x;          // cluster rank / column slice
    const int b0  = blockIdx.y * ROWS;
    const int j0  = c * COLS;

    const int ks = tid >> 5;             // warp = k-slice (0..15)
    const int jp = tid & 31;             // cols 2jp, 2jp+1
    const int jj = tid >> 2;             // reduce mapping (tid<256)
    const int bb = tid & 3;

    // ---- R slice into registers ----
    float rx[KROWS], ry[KROWS];
    {
        const float* rg = R + j0 + 2 * jp;
#pragma unroll
        for (int ii = 0; ii < KROWS; ii++) {
            float2 v = *(const float2*)(rg + (ks * KROWS + ii) * D_);
            rx[ii] = v.x; ry[ii] = v.y;
        }
    }

    // ---- init smem ----
    for (int idx = tid; idx < 3 * D_ * ROWS; idx += THREADS) hbuf[idx] = 0.0f;
    if (tid < COLS) {
        bias[tid] = b_ig[j0 + tid];
        wsl[tid]  = W_out[j0 + tid];
    }
    if (tid < 32) osum[tid] = 0.0f;
    if (tid == 0) {
        mbar_init(smem_u32 + MBAR_BYTE + 0,  1);
        mbar_init(smem_u32 + MBAR_BYTE + 8,  1);
        mbar_init(smem_u32 + MBAR_BYTE + 16, 1);
    }
    __syncthreads();
    if (tid == 0) {
        mbar_expect_tx(smem_u32 + MBAR_BYTE + 0,  STEP_TX);
        mbar_expect_tx(smem_u32 + MBAR_BYTE + 8,  STEP_TX);
        mbar_expect_tx(smem_u32 + MBAR_BYTE + 16, STEP_TX);
    }
    __syncthreads();
    asm volatile("barrier.cluster.arrive.aligned;" ::: "memory");
    asm volatile("barrier.cluster.wait.aligned;"   ::: "memory");

    // Peer smem bases
    uint32_t peer_base[CSZ];
#pragma unroll
    for (int p = 0; p < CSZ; p++) {
        asm volatile("mapa.shared::cluster.u32 %0, %1, %2;"
                     : "=r"(peer_base[p]) : "r"(smem_u32), "r"(p));
    }

    float racc = 0.0f;
    int cur = 0;
    uint32_t phases = 0;   // bit b = next wait parity for buffer b

    for (int t = 0; t < L_; t++) {
        const int nxt = (cur == 2) ? 0 : cur + 1;

        // prefetch ci (consumed after matvec)
        float civ = 0.0f;
        if (tid < 256)
            civ = __ldg(&g_ci[((b0 + bb) * L_ + t) * D_ + j0 + jj]);

        // deferred output partial from step t-1 (pre-wait, off critical path)
        if (t > 0 && tid < 4) {
            float s = 0.0f;
#pragma unroll
            for (int w = 0; w < 8; w++) s += osum[w * 4 + tid];
            racc += s;
            g_part[(b0 + tid) * (CSZ * L_) + c * L_ + (t - 1)] = racc;
        }

        // wait for h(t) remote slices (skip t=0: zeros written locally)
        if (t > 0) {
            mbar_wait_cta(smem_u32 + MBAR_BYTE + cur * 8, (phases >> cur) & 1u);
            phases ^= (1u << cur);
            // re-post expect for this buffer's NEXT fill round (at step t+2)
            if (tid == 256)
                mbar_expect_tx(smem_u32 + MBAR_BYTE + cur * 8, STEP_TX);
        }

        const float* hc = hbuf + cur * (D_ * ROWS);

        // ---- matvec: R from registers, h broadcast from smem ----
        {
            const ulonglong2* hvp = (const ulonglong2*)(hc + ks * KROWS * ROWS);
            unsigned long long a00 = 0, a01 = 0, a10 = 0, a11 = 0;
#pragma unroll
            for (int ii = 0; ii < KROWS; ii++) {
                ulonglong2 hv = hvp[ii];
                unsigned long long r0 = pk2(rx[ii], rx[ii]);
                unsigned long long r1 = pk2(ry[ii], ry[ii]);
                fma2(a00, r0, hv.x); fma2(a01, r0, hv.y);
                fma2(a10, r1, hv.x); fma2(a11, r1, hv.y);
            }
            float4 q0, q1;
            upk2(q0.x, q0.y, a00); upk2(q0.z, q0.w, a01);
            upk2(q1.x, q1.y, a10); upk2(q1.z, q1.w, a11);
            float* pb = pbuf + (ks * 32 + jp) * 8;
            *(float4*)(pb)     = q0;
            *(float4*)(pb + 4) = q1;
        }
        __syncthreads();

        // ---- reduce + gate + update: write h(t+1) own slice locally ----
        if (tid < 256) {
            float z = bias[jj];
#pragma unroll
            for (int s = 0; s < 16; s++) z += pbuf[s * 256 + tid];
            float ig = 1.0f / (1.0f + __expf(-z));
            float u  = civ * ig;
            float hval = hc[(j0 + jj) * 4 + bb] + u;
            hbuf[nxt * (D_ * ROWS) + (j0 + jj) * 4 + bb] = hval;

            float pp = u * wsl[jj];
            pp += __shfl_xor_sync(0xFFFFFFFF, pp, 4);
            pp += __shfl_xor_sync(0xFFFFFFFF, pp, 8);
            pp += __shfl_xor_sync(0xFFFFFFFF, pp, 16);
            if ((tid & 31) < 4)
                osum[(tid >> 5) * 4 + bb] = pp;
        }
        __syncthreads();

        // ---- DMA h(t+1) own slice to the 7 REMOTE peers (skip self) ----
        if (t + 1 < L_ && tid < CSZ && tid != c) {
            fence_proxy_async_cta();
            uint32_t off  = (uint32_t)(HBUF_OFF + nxt * (D_ * ROWS) + j0 * 4) * 4u;
            uint32_t moff = (uint32_t)(MBAR_BYTE + nxt * 8);
            bulk_dsmem(peer_base[tid] + off, smem_u32 + off, SLICE_BYTES,
                       peer_base[tid] + moff);
        }

        cur = nxt;
    }

    // final deferred output partial (t = L-1)
    if (tid < 4) {
        float s = 0.0f;
#pragma unroll
        for (int w = 0; w < 8; w++) s += osum[w * 4 + tid];
        racc += s;
        g_part[(b0 + tid) * (CSZ * L_) + c * L_ + (L_ - 1)] = racc;
    }

    asm volatile("barrier.cluster.arrive.aligned;" ::: "memory");
    asm volatile("barrier.cluster.wait.aligned;"   ::: "memory");
}

// ============================================================================
// Kernel 3: out[b,t] = b_out + sum_c g_part[b][c][t]
// ============================================================================
__global__ __launch_bounds__(256)
void k_out(const float* __restrict__ b_out, float* __restrict__ out)
{
    int i = blockIdx.x * 256 + threadIdx.x;
    int b = i >> 9, t = i & 511;
    float s = b_out[0];
#pragma unroll
    for (int cc = 0; cc < CSZ; cc++) s += g_part[b * (CSZ * L_) + cc * L_ + t];
    out[i] = s;
}

// ============================================================================
extern "C" void kernel_launch(void* const* d_in, const int* in_sizes, int n_in,
                              void* d_out, int out_size)
{
    const float* obs  = (const float*)d_in[0];
    const float* act  = (const float*)d_in[1];
    const float* W_ci = (const float*)d_in[2];
    const float* b_ci = (const float*)d_in[3];
    const float* R    = (const float*)d_in[4];
    const float* bg   = (const float*)d_in[5];
    const float* W_o  = (const float*)d_in[6];
    const float* b_o  = (const float*)d_in[7];
    float* out = (float*)d_out;

    cudaFuncSetAttribute(k_ci, cudaFuncAttributeMaxDynamicSharedMemorySize, KCI_SMEM);
    k_ci<<<dim3(4, 256), 256, KCI_SMEM>>>(obs, act, W_ci, b_ci);

    cudaFuncSetAttribute(k_scan, cudaFuncAttributeMaxDynamicSharedMemorySize, SMEM_BYTES);
    k_scan<<<dim3(CSZ, NCL), THREADS, SMEM_BYTES>>>(R, bg, W_o);

    k_out<<<128, 256>>>(b_o, out);
}